// round 2
// baseline (speedup 1.0000x reference)
#include <cuda_runtime.h>
#include <math.h>

#define N_NODES 50000
#define N_EDGES 1600000
#define F_IN    1433
#define HID     16
#define OUTC    7

// ---------------- scratch (device globals; no allocation allowed) ----------------
__device__ float g_B1 [F_IN * 80];        // packed [W1 (64 cols: k*16+o) | root1 (16 cols)]
__device__ float g_W2c[16 * 35];          // packed [W2 (28 cols: k*7+o) | root2 (7 cols)]
__device__ float g_h1 [N_NODES * 80];     // layer1 node transform (+ root part in cols 64..79)
__device__ float g_agg1[N_NODES * 16];
__device__ float g_h  [N_NODES * 16];     // post-ELU hidden
__device__ float g_h2 [N_NODES * 40];     // layer2 transform, padded: k*8+o (o<7), 32+o = root part
__device__ float g_agg2[N_NODES * 8];     // padded stride 8 for aligned vector REDs
__device__ int   g_deg[N_NODES];

// ---------------- zero scratch accumulators ----------------
__global__ void zero_kernel() {
    int idx = blockIdx.x * blockDim.x + threadIdx.x;
    if (idx < N_NODES * 16) g_agg1[idx] = 0.f;
    if (idx < N_NODES * 8)  g_agg2[idx] = 0.f;
    if (idx < N_NODES)      g_deg[idx]  = 0;
}

// ---------------- pack weight matrices ----------------
__global__ void prep_kernel(const float* __restrict__ W1, const float* __restrict__ root1,
                            const float* __restrict__ W2, const float* __restrict__ root2) {
    int idx = blockIdx.x * blockDim.x + threadIdx.x;
    const int total1 = F_IN * 80;
    if (idx < total1) {
        int f = idx / 80, c = idx % 80;
        float v;
        if (c < 64) { int k = c >> 4, o = c & 15; v = W1[(k * F_IN + f) * HID + o]; }
        else        { v = root1[f * HID + (c - 64)]; }
        g_B1[idx] = v;
    } else {
        int j = idx - total1;
        if (j < 16 * 35) {
            int f = j / 35, c = j % 35;
            float v;
            if (c < 28) { int k = c / 7, o = c % 7; v = W2[(k * HID + f) * OUTC + o]; }
            else        { v = root2[f * OUTC + (c - 28)]; }
            g_W2c[j] = v;
        }
    }
}

// ---------------- in-degree ----------------
__global__ void deg_kernel(const int* __restrict__ ei) {
    int e = blockIdx.x * blockDim.x + threadIdx.x;
    if (e < N_EDGES) atomicAdd(&g_deg[ei[N_EDGES + e]], 1);
}

// ---------------- GEMM1: h1[N,80] = x[N,1433] @ B1[1433,80] ----------------
// BM=128, BN=80, BK=16. 256 threads; each thread: 8 rows x 5 cols.
// A tile stored transposed As[k][row] with row-pad 132 so the 8 row-operands
// are fetched as 2x LDS.128 (aligned: kk*132 is a multiple of 4 floats).
#define BM 128
#define BKQ 16
#define APAD 132
__global__ void __launch_bounds__(256) gemm1_kernel(const float* __restrict__ A) {
    __shared__ float As[BKQ][APAD];   // [k][row], padded
    __shared__ float Bs[BKQ][80];
    int tid  = threadIdx.x;
    int brow = blockIdx.x * BM;
    int tx = tid & 15, ty = tid >> 4;   // tx: 16 col-groups of 5; ty: 16 row-groups of 8
    float acc[8][5] = {};
    for (int kt = 0; kt < F_IN; kt += BKQ) {
        // load A tile 128x16 (coalesced: consecutive tid -> consecutive k-col), store transposed
        #pragma unroll
        for (int i = 0; i < 8; i++) {
            int idx = tid + i * 256;
            int r = idx >> 4, c = idx & 15;
            int gr = brow + r, gc = kt + c;
            As[c][r] = (gr < N_NODES && gc < F_IN) ? A[(long)gr * F_IN + gc] : 0.f;
        }
        // load B tile 16x80
        #pragma unroll
        for (int i = 0; i < 5; i++) {
            int idx = tid + i * 256;
            int r = idx / 80, c = idx % 80;
            int gr = kt + r;
            Bs[r][c] = (gr < F_IN) ? g_B1[gr * 80 + c] : 0.f;
        }
        __syncthreads();
        #pragma unroll
        for (int kk = 0; kk < BKQ; kk++) {
            float4 a0 = *(const float4*)&As[kk][ty * 8];
            float4 a1 = *(const float4*)&As[kk][ty * 8 + 4];
            float a[8] = {a0.x, a0.y, a0.z, a0.w, a1.x, a1.y, a1.z, a1.w};
            float b[5];
            #pragma unroll
            for (int j = 0; j < 5; j++) b[j] = Bs[kk][tx * 5 + j];
            #pragma unroll
            for (int i = 0; i < 8; i++)
                #pragma unroll
                for (int j = 0; j < 5; j++)
                    acc[i][j] += a[i] * b[j];
        }
        __syncthreads();
    }
    #pragma unroll
    for (int i = 0; i < 8; i++) {
        int gr = brow + ty * 8 + i;
        if (gr < N_NODES) {
            #pragma unroll
            for (int j = 0; j < 5; j++)
                g_h1[gr * 80 + tx * 5 + j] = acc[i][j];
        }
    }
}

// ---------------- edge pass 1: gather h1[src], basis-weight, scatter to agg1 ----------------
__global__ void edge1_kernel(const int* __restrict__ ei, const float* __restrict__ pseudo) {
    int gid = blockIdx.x * blockDim.x + threadIdx.x;
    if (gid >= N_EDGES * 4) return;
    int e = gid >> 2, j = gid & 3;                 // 4 threads per edge, float4 each
    int s = ei[e], d = ei[N_EDGES + e];
    float2 uv = ((const float2*)pseudo)[e];
    float u = uv.x, v = uv.y;
    float b0 = (1.f - u) * (1.f - v);
    float b1 = (1.f - u) * v;
    float b2 = u * (1.f - v);
    float b3 = u * v;
    const float4* hp = (const float4*)(g_h1 + s * 80 + j * 4);
    float4 f0 = hp[0], f1 = hp[4], f2 = hp[8], f3 = hp[12];   // k*16 stride = 4 float4s
    float4 m;
    m.x = b0 * f0.x + b1 * f1.x + b2 * f2.x + b3 * f3.x;
    m.y = b0 * f0.y + b1 * f1.y + b2 * f2.y + b3 * f3.y;
    m.z = b0 * f0.z + b1 * f1.z + b2 * f2.z + b3 * f3.z;
    m.w = b0 * f0.w + b1 * f1.w + b2 * f2.w + b3 * f3.w;
    float* dst = g_agg1 + d * 16 + j * 4;
    asm volatile("red.global.add.v4.f32 [%0], {%1,%2,%3,%4};"
                 :: "l"(dst), "f"(m.x), "f"(m.y), "f"(m.z), "f"(m.w) : "memory");
}

// ---------------- mean + root + ELU ----------------
__global__ void elu_kernel() {
    int idx = blockIdx.x * blockDim.x + threadIdx.x;
    if (idx >= N_NODES * 16) return;
    int n = idx >> 4, o = idx & 15;
    int dg = g_deg[n];
    float inv = dg > 0 ? 1.f / (float)dg : 0.f;
    float t = g_agg1[idx] * inv + g_h1[n * 80 + 64 + o];
    g_h[idx] = t > 0.f ? t : expm1f(t);
}

// ---------------- GEMM2: h2[N,35] = h[N,16] @ W2c[16,35] (padded store) ----------------
__global__ void __launch_bounds__(256) gemm2_kernel() {
    __shared__ float hs[64][16];
    __shared__ float w[16 * 35];
    int tid  = threadIdx.x;
    int base = blockIdx.x * 64;
    for (int i = tid; i < 64 * 16; i += 256) {
        int n = base + (i >> 4);
        hs[i >> 4][i & 15] = (n < N_NODES) ? g_h[n * 16 + (i & 15)] : 0.f;
    }
    for (int i = tid; i < 16 * 35; i += 256) w[i] = g_W2c[i];
    __syncthreads();
    for (int idx = tid; idx < 64 * 35; idx += 256) {
        int r = idx / 35, c = idx % 35;
        int n = base + r;
        if (n >= N_NODES) continue;
        float sum = 0.f;
        #pragma unroll
        for (int f = 0; f < 16; f++) sum += hs[r][f] * w[f * 35 + c];
        int pc = (c < 28) ? ((c / 7) * 8 + (c % 7)) : (32 + (c - 28));
        g_h2[n * 40 + pc] = sum;
    }
}

// ---------------- edge pass 2 ----------------
__global__ void edge2_kernel(const int* __restrict__ ei, const float* __restrict__ pseudo) {
    int gid = blockIdx.x * blockDim.x + threadIdx.x;
    if (gid >= N_EDGES * 2) return;
    int e = gid >> 1, j = gid & 1;                 // 2 threads per edge: o[0..3], o[4..6]
    int s = ei[e], d = ei[N_EDGES + e];
    float2 uv = ((const float2*)pseudo)[e];
    float u = uv.x, v = uv.y;
    float b0 = (1.f - u) * (1.f - v);
    float b1 = (1.f - u) * v;
    float b2 = u * (1.f - v);
    float b3 = u * v;
    const float* row = g_h2 + s * 40;
    if (j == 0) {
        float4 f0 = *(const float4*)(row);
        float4 f1 = *(const float4*)(row + 8);
        float4 f2 = *(const float4*)(row + 16);
        float4 f3 = *(const float4*)(row + 24);
        float4 m;
        m.x = b0 * f0.x + b1 * f1.x + b2 * f2.x + b3 * f3.x;
        m.y = b0 * f0.y + b1 * f1.y + b2 * f2.y + b3 * f3.y;
        m.z = b0 * f0.z + b1 * f1.z + b2 * f2.z + b3 * f3.z;
        m.w = b0 * f0.w + b1 * f1.w + b2 * f2.w + b3 * f3.w;
        float* dst = g_agg2 + d * 8;
        asm volatile("red.global.add.v4.f32 [%0], {%1,%2,%3,%4};"
                     :: "l"(dst), "f"(m.x), "f"(m.y), "f"(m.z), "f"(m.w) : "memory");
    } else {
        float2 f0 = *(const float2*)(row + 4);
        float2 f1 = *(const float2*)(row + 12);
        float2 f2 = *(const float2*)(row + 20);
        float2 f3 = *(const float2*)(row + 28);
        float2 m;
        m.x = b0 * f0.x + b1 * f1.x + b2 * f2.x + b3 * f3.x;
        m.y = b0 * f0.y + b1 * f1.y + b2 * f2.y + b3 * f3.y;
        float ms = b0 * row[6] + b1 * row[14] + b2 * row[22] + b3 * row[30];
        float* dst = g_agg2 + d * 8 + 4;
        asm volatile("red.global.add.v2.f32 [%0], {%1,%2};"
                     :: "l"(dst), "f"(m.x), "f"(m.y) : "memory");
        atomicAdd(g_agg2 + d * 8 + 6, ms);
    }
}

// ---------------- mean + root + log_softmax ----------------
__global__ void final_kernel(float* __restrict__ out) {
    int n = blockIdx.x * blockDim.x + threadIdx.x;
    if (n >= N_NODES) return;
    int dg = g_deg[n];
    float inv = dg > 0 ? 1.f / (float)dg : 0.f;
    float vals[OUTC];
    float mx = -INFINITY;
    #pragma unroll
    for (int c = 0; c < OUTC; c++) {
        float t = g_agg2[n * 8 + c] * inv + g_h2[n * 40 + 32 + c];
        vals[c] = t;
        mx = fmaxf(mx, t);
    }
    float se = 0.f;
    #pragma unroll
    for (int c = 0; c < OUTC; c++) se += expf(vals[c] - mx);
    float lse = mx + logf(se);
    #pragma unroll
    for (int c = 0; c < OUTC; c++) out[n * OUTC + c] = vals[c] - lse;
}

// ---------------- launch ----------------
extern "C" void kernel_launch(void* const* d_in, const int* in_sizes, int n_in,
                              void* d_out, int out_size) {
    const float* x      = (const float*)d_in[0];
    const int*   ei     = (const int*)  d_in[1];
    const float* pseudo = (const float*)d_in[2];
    const float* W1     = (const float*)d_in[3];
    const float* root1  = (const float*)d_in[4];
    const float* W2     = (const float*)d_in[5];
    const float* root2  = (const float*)d_in[6];
    float* out = (float*)d_out;

    zero_kernel<<<(N_NODES * 16 + 255) / 256, 256>>>();
    prep_kernel<<<(F_IN * 80 + 16 * 35 + 255) / 256, 256>>>(W1, root1, W2, root2);
    deg_kernel<<<(N_EDGES + 255) / 256, 256>>>(ei);
    gemm1_kernel<<<(N_NODES + BM - 1) / BM, 256>>>(x);
    edge1_kernel<<<(N_EDGES * 4 + 255) / 256, 256>>>(ei, pseudo);
    elu_kernel<<<(N_NODES * 16 + 255) / 256, 256>>>();
    gemm2_kernel<<<(N_NODES + 63) / 64, 256>>>();
    edge2_kernel<<<(N_EDGES * 2 + 255) / 256, 256>>>(ei, pseudo);
    final_kernel<<<(N_NODES + 255) / 256, 256>>>(out);
}

// round 6
// speedup vs baseline: 1.5885x; 1.5885x over previous
#include <cuda_runtime.h>
#include <cuda_bf16.h>
#include <math.h>
#include <stdint.h>

#define N_NODES 50000
#define N_EDGES 1600000
#define F_IN    1433
#define HID     16
#define OUTC    7

#define BK      32
#define NCH     45              // ceil(1433/32)
#define KPAD    (NCH*BK)        // 1440
#define BM      128
#define BN      80

// ---------------- scratch (device globals) ----------------
__device__ __nv_bfloat16 g_Bhi[BN * KPAD];   // [n=80][f] bf16 hi, zero-padded
__device__ __nv_bfloat16 g_Blo[BN * KPAD];   // [n=80][f] bf16 lo
__device__ float g_W2c[16 * 35];             // packed [W2 (28: k*7+o) | root2 (7)]
__device__ float g_h1 [N_NODES * 80];        // layer1 transform (+root in 64..79)
__device__ float g_agg1[N_NODES * 16];
__device__ float g_h  [N_NODES * 16];
__device__ float g_h2 [N_NODES * 40];        // padded: k*8+o (o<7), 32+o = root
__device__ float g_agg2[N_NODES * 8];
__device__ int   g_deg[N_NODES];

// ---------------- helpers ----------------
__device__ __forceinline__ uint32_t smem_u32(const void* p) {
    uint32_t a;
    asm("{ .reg .u64 t; cvta.to.shared.u64 t, %1; cvt.u32.u64 %0, t; }" : "=r"(a) : "l"(p));
    return a;
}

#define LDSM_X4(r0, r1, r2, r3, a) \
    asm volatile("ldmatrix.sync.aligned.m8n8.x4.shared.b16 {%0,%1,%2,%3}, [%4];" \
        : "=r"(r0), "=r"(r1), "=r"(r2), "=r"(r3) : "r"(a))
#define LDSM_X2(r0, r1, a) \
    asm volatile("ldmatrix.sync.aligned.m8n8.x2.shared.b16 {%0,%1}, [%2];" \
        : "=r"(r0), "=r"(r1) : "r"(a))

#define MMA_BF16(c, a, b) \
    asm volatile("mma.sync.aligned.m16n8k16.row.col.f32.bf16.bf16.f32 " \
        "{%0,%1,%2,%3}, {%4,%5,%6,%7}, {%8,%9}, {%0,%1,%2,%3};" \
        : "+f"((c)[0]), "+f"((c)[1]), "+f"((c)[2]), "+f"((c)[3]) \
        : "r"((a)[0]), "r"((a)[1]), "r"((a)[2]), "r"((a)[3]), "r"((b)[0]), "r"((b)[1]))

__device__ __forceinline__ uint32_t pack_hi(float v0, float v1, uint32_t& lo_out) {
    __nv_bfloat16 h0 = __float2bfloat16_rn(v0);
    __nv_bfloat16 h1 = __float2bfloat16_rn(v1);
    __nv_bfloat16 l0 = __float2bfloat16_rn(v0 - __bfloat162float(h0));
    __nv_bfloat16 l1 = __float2bfloat16_rn(v1 - __bfloat162float(h1));
    lo_out = ((uint32_t)__bfloat16_as_ushort(l1) << 16) | __bfloat16_as_ushort(l0);
    return ((uint32_t)__bfloat16_as_ushort(h1) << 16) | __bfloat16_as_ushort(h0);
}

// ---------------- zero scratch accumulators ----------------
__global__ void zero_kernel() {
    int idx = blockIdx.x * blockDim.x + threadIdx.x;
    if (idx < N_NODES * 16) g_agg1[idx] = 0.f;
    if (idx < N_NODES * 8)  g_agg2[idx] = 0.f;
    if (idx < N_NODES)      g_deg[idx]  = 0;
}

// ---------------- pack weights: bf16 hi/lo for layer1, fp32 for layer2 ----------------
__global__ void prep_kernel(const float* __restrict__ W1, const float* __restrict__ root1,
                            const float* __restrict__ W2, const float* __restrict__ root2) {
    int idx = blockIdx.x * blockDim.x + threadIdx.x;
    const int total1 = BN * KPAD;
    if (idx < total1) {
        int n = idx / KPAD, f = idx % KPAD;
        float v = 0.f;
        if (f < F_IN) {
            if (n < 64) { int k = n >> 4, o = n & 15; v = W1[(k * F_IN + f) * HID + o]; }
            else        { v = root1[f * HID + (n - 64)]; }
        }
        __nv_bfloat16 hi = __float2bfloat16_rn(v);
        __nv_bfloat16 lo = __float2bfloat16_rn(v - __bfloat162float(hi));
        g_Bhi[idx] = hi;
        g_Blo[idx] = lo;
    } else {
        int j = idx - total1;
        if (j < 16 * 35) {
            int f = j / 35, c = j % 35;
            float v;
            if (c < 28) { int k = c / 7, o = c % 7; v = W2[(k * HID + f) * OUTC + o]; }
            else        { v = root2[f * OUTC + (c - 28)]; }
            g_W2c[j] = v;
        }
    }
}

// ---------------- in-degree ----------------
__global__ void deg_kernel(const int* __restrict__ ei) {
    int e = blockIdx.x * blockDim.x + threadIdx.x;
    if (e < N_EDGES) atomicAdd(&g_deg[ei[N_EDGES + e]], 1);
}

// ---------------- GEMM1 via mma.sync bf16 (3-term split, fp32 accum) ----------------
// h1[N,80] = x[N,1433] @ B1[1433,80]
// smem rows stride 40 bf16 = 80 bytes (conflict-free for ldmatrix 8-row access)
#define RS 40   // row stride in bf16 elems
__global__ void __launch_bounds__(256) gemm1_mma(const float* __restrict__ A) {
    __shared__ __align__(16) __nv_bfloat16 As_hi[BM * RS];
    __shared__ __align__(16) __nv_bfloat16 As_lo[BM * RS];
    __shared__ __align__(16) __nv_bfloat16 Bs_hi[BN * RS];
    __shared__ __align__(16) __nv_bfloat16 Bs_lo[BN * RS];

    int tid  = threadIdx.x;
    int lane = tid & 31, wid = tid >> 5;
    int wm = wid & 3, wn = wid >> 2;       // warp grid 4(m) x 2(n)
    int m0 = wm * 32, n0 = wn * 40;
    long brow = (long)blockIdx.x * BM;
    bool full_rows = (brow + BM <= N_NODES);

    uint32_t sAhi = smem_u32(As_hi), sAlo = smem_u32(As_lo);
    uint32_t sBhi = smem_u32(Bs_hi), sBlo = smem_u32(Bs_lo);

    float acc[2][5][4];
    #pragma unroll
    for (int i = 0; i < 2; i++)
        #pragma unroll
        for (int j = 0; j < 5; j++)
            #pragma unroll
            for (int q = 0; q < 4; q++) acc[i][j][q] = 0.f;

    for (int c = 0; c < NCH; c++) {
        int kt = c * BK;
        // ---- A chunk: 128 rows x 32 cols fp32 -> split bf16 hi/lo
        bool full = full_rows && (kt + BK <= F_IN);
        #pragma unroll
        for (int i = 0; i < 4; i++) {
            int f = tid + i * 256;          // 0..1023 : float4-group index
            int row = f >> 3, c4 = f & 7;   // row 0..127, c4 0..7
            long gr = brow + row;
            int gc = kt + c4 * 4;
            float v0, v1, v2, v3;
            if (full) {
                const float* xp = A + gr * F_IN + gc;
                v0 = xp[0]; v1 = xp[1]; v2 = xp[2]; v3 = xp[3];
            } else {
                v0 = v1 = v2 = v3 = 0.f;
                if (gr < N_NODES) {
                    const float* xp = A + gr * F_IN + gc;
                    if (gc     < F_IN) v0 = xp[0];
                    if (gc + 1 < F_IN) v1 = xp[1];
                    if (gc + 2 < F_IN) v2 = xp[2];
                    if (gc + 3 < F_IN) v3 = xp[3];
                }
            }
            uint32_t l01, l23;
            uint32_t h01 = pack_hi(v0, v1, l01);
            uint32_t h23 = pack_hi(v2, v3, l23);
            uint32_t off = (uint32_t)(row * 80 + c4 * 8);
            *(uint2*)((char*)As_hi + off) = make_uint2(h01, h23);
            *(uint2*)((char*)As_lo + off) = make_uint2(l01, l23);
        }
        // ---- B chunk: 80 rows x 32 cols bf16 (pre-split in gmem)
        const uint32_t* bh = (const uint32_t*)g_Bhi;
        const uint32_t* bl = (const uint32_t*)g_Blo;
        #pragma unroll
        for (int i = 0; i < 5; i++) {
            int p = tid + i * 256;          // 0..1279 : bf16-pair index
            int row = p >> 4, c2 = p & 15;
            uint32_t src = (uint32_t)((row * KPAD + kt) >> 1) + c2;
            uint32_t off = (uint32_t)(row * 80 + c2 * 4);
            *(uint32_t*)((char*)Bs_hi + off) = bh[src];
            *(uint32_t*)((char*)Bs_lo + off) = bl[src];
        }
        __syncthreads();

        // ---- compute: 2 k-steps of 16
        #pragma unroll
        for (int ks = 0; ks < 2; ks++) {
            uint32_t ah[2][4], al[2][4];
            #pragma unroll
            for (int i = 0; i < 2; i++) {
                uint32_t roff = (uint32_t)((m0 + i * 16 + (lane & 15)) * 80
                                           + ks * 32 + ((lane >> 4) & 1) * 16);
                LDSM_X4(ah[i][0], ah[i][1], ah[i][2], ah[i][3], sAhi + roff);
                LDSM_X4(al[i][0], al[i][1], al[i][2], al[i][3], sAlo + roff);
            }
            uint32_t bhf[5][2], blf[5][2];
            #pragma unroll
            for (int j = 0; j < 5; j++) {
                uint32_t roff = (uint32_t)((n0 + j * 8 + (lane & 7)) * 80
                                           + ks * 32 + ((lane >> 3) & 1) * 16);
                LDSM_X2(bhf[j][0], bhf[j][1], sBhi + roff);
                LDSM_X2(blf[j][0], blf[j][1], sBlo + roff);
            }
            #pragma unroll
            for (int i = 0; i < 2; i++)
                #pragma unroll
                for (int j = 0; j < 5; j++) {
                    MMA_BF16(acc[i][j], ah[i], bhf[j]);
                    MMA_BF16(acc[i][j], al[i], bhf[j]);
                    MMA_BF16(acc[i][j], ah[i], blf[j]);
                }
        }
        __syncthreads();
    }

    // ---- epilogue: m16n8 accum layout -> g_h1
    #pragma unroll
    for (int i = 0; i < 2; i++) {
        long r0 = brow + m0 + i * 16 + (lane >> 2);
        long r1 = r0 + 8;
        #pragma unroll
        for (int j = 0; j < 5; j++) {
            int col = n0 + j * 8 + 2 * (lane & 3);
            if (r0 < N_NODES)
                *(float2*)(g_h1 + r0 * 80 + col) = make_float2(acc[i][j][0], acc[i][j][1]);
            if (r1 < N_NODES)
                *(float2*)(g_h1 + r1 * 80 + col) = make_float2(acc[i][j][2], acc[i][j][3]);
        }
    }
}

// ---------------- edge pass 1: gather h1[src], basis-weight, scatter to agg1 ----------------
__global__ void edge1_kernel(const int* __restrict__ ei, const float* __restrict__ pseudo) {
    int gid = blockIdx.x * blockDim.x + threadIdx.x;
    if (gid >= N_EDGES * 4) return;
    int e = gid >> 2, j = gid & 3;
    int s = ei[e], d = ei[N_EDGES + e];
    float2 uv = ((const float2*)pseudo)[e];
    float u = uv.x, v = uv.y;
    float b0 = (1.f - u) * (1.f - v);
    float b1 = (1.f - u) * v;
    float b2 = u * (1.f - v);
    float b3 = u * v;
    const float4* hp = (const float4*)(g_h1 + s * 80 + j * 4);
    float4 f0 = hp[0], f1 = hp[4], f2 = hp[8], f3 = hp[12];
    float4 m;
    m.x = b0 * f0.x + b1 * f1.x + b2 * f2.x + b3 * f3.x;
    m.y = b0 * f0.y + b1 * f1.y + b2 * f2.y + b3 * f3.y;
    m.z = b0 * f0.z + b1 * f1.z + b2 * f2.z + b3 * f3.z;
    m.w = b0 * f0.w + b1 * f1.w + b2 * f2.w + b3 * f3.w;
    float* dst = g_agg1 + d * 16 + j * 4;
    asm volatile("red.global.add.v4.f32 [%0], {%1,%2,%3,%4};"
                 :: "l"(dst), "f"(m.x), "f"(m.y), "f"(m.z), "f"(m.w) : "memory");
}

// ---------------- mean + root + ELU ----------------
__global__ void elu_kernel() {
    int idx = blockIdx.x * blockDim.x + threadIdx.x;
    if (idx >= N_NODES * 16) return;
    int n = idx >> 4, o = idx & 15;
    int dg = g_deg[n];
    float inv = dg > 0 ? 1.f / (float)dg : 0.f;
    float t = g_agg1[idx] * inv + g_h1[n * 80 + 64 + o];
    g_h[idx] = t > 0.f ? t : expm1f(t);
}

// ---------------- GEMM2: h2[N,35] = h[N,16] @ W2c[16,35] (padded store) ----------------
__global__ void __launch_bounds__(256) gemm2_kernel() {
    __shared__ float hs[64][16];
    __shared__ float w[16 * 35];
    int tid  = threadIdx.x;
    int base = blockIdx.x * 64;
    for (int i = tid; i < 64 * 16; i += 256) {
        int n = base + (i >> 4);
        hs[i >> 4][i & 15] = (n < N_NODES) ? g_h[n * 16 + (i & 15)] : 0.f;
    }
    for (int i = tid; i < 16 * 35; i += 256) w[i] = g_W2c[i];
    __syncthreads();
    for (int idx = tid; idx < 64 * 35; idx += 256) {
        int r = idx / 35, c = idx % 35;
        int n = base + r;
        if (n >= N_NODES) continue;
        float sum = 0.f;
        #pragma unroll
        for (int f = 0; f < 16; f++) sum += hs[r][f] * w[f * 35 + c];
        int pc = (c < 28) ? ((c / 7) * 8 + (c % 7)) : (32 + (c - 28));
        g_h2[n * 40 + pc] = sum;
    }
}

// ---------------- edge pass 2 ----------------
__global__ void edge2_kernel(const int* __restrict__ ei, const float* __restrict__ pseudo) {
    int gid = blockIdx.x * blockDim.x + threadIdx.x;
    if (gid >= N_EDGES * 2) return;
    int e = gid >> 1, j = gid & 1;
    int s = ei[e], d = ei[N_EDGES + e];
    float2 uv = ((const float2*)pseudo)[e];
    float u = uv.x, v = uv.y;
    float b0 = (1.f - u) * (1.f - v);
    float b1 = (1.f - u) * v;
    float b2 = u * (1.f - v);
    float b3 = u * v;
    const float* row = g_h2 + s * 40;
    if (j == 0) {
        float4 f0 = *(const float4*)(row);
        float4 f1 = *(const float4*)(row + 8);
        float4 f2 = *(const float4*)(row + 16);
        float4 f3 = *(const float4*)(row + 24);
        float4 m;
        m.x = b0 * f0.x + b1 * f1.x + b2 * f2.x + b3 * f3.x;
        m.y = b0 * f0.y + b1 * f1.y + b2 * f2.y + b3 * f3.y;
        m.z = b0 * f0.z + b1 * f1.z + b2 * f2.z + b3 * f3.z;
        m.w = b0 * f0.w + b1 * f1.w + b2 * f2.w + b3 * f3.w;
        float* dst = g_agg2 + d * 8;
        asm volatile("red.global.add.v4.f32 [%0], {%1,%2,%3,%4};"
                     :: "l"(dst), "f"(m.x), "f"(m.y), "f"(m.z), "f"(m.w) : "memory");
    } else {
        float2 f0 = *(const float2*)(row + 4);
        float2 f1 = *(const float2*)(row + 12);
        float2 f2 = *(const float2*)(row + 20);
        float2 f3 = *(const float2*)(row + 28);
        float2 m;
        m.x = b0 * f0.x + b1 * f1.x + b2 * f2.x + b3 * f3.x;
        m.y = b0 * f0.y + b1 * f1.y + b2 * f2.y + b3 * f3.y;
        float ms = b0 * row[6] + b1 * row[14] + b2 * row[22] + b3 * row[30];
        float* dst = g_agg2 + d * 8 + 4;
        asm volatile("red.global.add.v2.f32 [%0], {%1,%2};"
                     :: "l"(dst), "f"(m.x), "f"(m.y) : "memory");
        atomicAdd(g_agg2 + d * 8 + 6, ms);
    }
}

// ---------------- mean + root + log_softmax ----------------
__global__ void final_kernel(float* __restrict__ out) {
    int n = blockIdx.x * blockDim.x + threadIdx.x;
    if (n >= N_NODES) return;
    int dg = g_deg[n];
    float inv = dg > 0 ? 1.f / (float)dg : 0.f;
    float vals[OUTC];
    float mx = -INFINITY;
    #pragma unroll
    for (int c = 0; c < OUTC; c++) {
        float t = g_agg2[n * 8 + c] * inv + g_h2[n * 40 + 32 + c];
        vals[c] = t;
        mx = fmaxf(mx, t);
    }
    float se = 0.f;
    #pragma unroll
    for (int c = 0; c < OUTC; c++) se += expf(vals[c] - mx);
    float lse = mx + logf(se);
    #pragma unroll
    for (int c = 0; c < OUTC; c++) out[n * OUTC + c] = vals[c] - lse;
}

// ---------------- launch ----------------
extern "C" void kernel_launch(void* const* d_in, const int* in_sizes, int n_in,
                              void* d_out, int out_size) {
    const float* x      = (const float*)d_in[0];
    const int*   ei     = (const int*)  d_in[1];
    const float* pseudo = (const float*)d_in[2];
    const float* W1     = (const float*)d_in[3];
    const float* root1  = (const float*)d_in[4];
    const float* W2     = (const float*)d_in[5];
    const float* root2  = (const float*)d_in[6];
    float* out = (float*)d_out;

    zero_kernel<<<(N_NODES * 16 + 255) / 256, 256>>>();
    prep_kernel<<<(BN * KPAD + 16 * 35 + 255) / 256, 256>>>(W1, root1, W2, root2);
    deg_kernel<<<(N_EDGES + 255) / 256, 256>>>(ei);
    gemm1_mma<<<(N_NODES + BM - 1) / BM, 256>>>(x);
    edge1_kernel<<<(N_EDGES * 4 + 255) / 256, 256>>>(ei, pseudo);
    elu_kernel<<<(N_NODES * 16 + 255) / 256, 256>>>();
    gemm2_kernel<<<(N_NODES + 63) / 64, 256>>>();
    edge2_kernel<<<(N_EDGES * 2 + 255) / 256, 256>>>(ei, pseudo);
    final_kernel<<<(N_NODES + 255) / 256, 256>>>(out);
}